// round 11
// baseline (speedup 1.0000x reference)
#include <cuda_runtime.h>
#include <cuda_bf16.h>
#include <cstdint>

#define N_USER 100000
#define N_ITEM 50000
#define N_TOTAL (N_USER + N_ITEM)   // 150000
#define D 64
#define NNZ 4000000
#define B 2048
#define NEG (4 * B)                  // 8192
#define NSLOTS (B + B + NEG)         // 12288
#define NWORDS ((N_TOTAL + 31) / 32) // 4688 words = 18.75 KB bitset
#define MAXDEG 128                   // mean deg ~26.7; P(>127) ~ 1e-42

#define EPT 4
#define SCAN_THREADS 256
#define EPB (SCAN_THREADS * EPT)     // 1024 edges per block

// Device scratch (zero-init at load).
// g_rowmap: row -> owner slot + 1. Never reset (only freshly flagged rows probed).
// g_cnt: per-slot bucket fill; zeroed by the slot's own thread in K1 each call.
// g_flags: needed-row bitset; K3 restores all-zero each call.
__device__ int      g_rowmap[N_TOTAL];                 // 600 KB
__device__ int      g_cnt[NSLOTS];
__device__ int2     g_edges[(size_t)NSLOTS * MAXDEG];  // (col, val bits), 12.6 MB
__device__ unsigned g_flags[NWORDS];

// slot -> global row id in [0, N_TOTAL)
__device__ __forceinline__ int slot_row(int s, const int* __restrict__ users,
                                        const int* __restrict__ pos,
                                        const int* __restrict__ neg) {
    if (s < B) return users[s];
    if (s < 2 * B) return N_USER + pos[s - B];
    return N_USER + neg[s - 2 * B];
}

// ---------------------------------------------------------------------------
// K1: claim rows + set flags + zero bucket counters. Tiny.
// ---------------------------------------------------------------------------
__global__ void k_claim(const int* __restrict__ users,
                        const int* __restrict__ pos,
                        const int* __restrict__ neg) {
    int s = blockIdx.x * blockDim.x + threadIdx.x;
    if (s >= NSLOTS) return;
    int r = slot_row(s, users, pos, neg);
    g_rowmap[r] = s + 1;                       // racing stores: any winner OK
    g_cnt[s] = 0;
    atomicOr(&g_flags[r >> 5], 1u << (r & 31));
}

// ---------------------------------------------------------------------------
// K2 (PDL): stream all edge records pre-sync, then probe flags and append
// hits (col, val) to the final owner's bucket.
// ---------------------------------------------------------------------------
__global__ void __launch_bounds__(SCAN_THREADS)
k_build(const int* __restrict__ adj_row,
        const int* __restrict__ adj_col,
        const float* __restrict__ adj_val) {
    int base = (blockIdx.x * SCAN_THREADS + threadIdx.x) * EPT;
    int4 r4 = make_int4(0, 0, 0, 0);
    int4 c4 = make_int4(0, 0, 0, 0);
    float4 v4 = make_float4(0.f, 0.f, 0.f, 0.f);
    bool valid = (base < NNZ);                 // NNZ % 4 == 0 -> full int4
    if (valid) {                               // dependency-free prefetch
        r4 = __ldcs(reinterpret_cast<const int4*>(adj_row) + (base >> 2));
        c4 = __ldcs(reinterpret_cast<const int4*>(adj_col) + (base >> 2));
        v4 = __ldcs(reinterpret_cast<const float4*>(adj_val) + (base >> 2));
    }

    cudaGridDependencySynchronize();           // wait for K1 (flags/rowmap/cnt)

    if (!valid) return;
    int   rr[EPT] = {r4.x, r4.y, r4.z, r4.w};
    int   cc[EPT] = {c4.x, c4.y, c4.z, c4.w};
    float vv[EPT] = {v4.x, v4.y, v4.z, v4.w};
#pragma unroll
    for (int k = 0; k < EPT; k++) {
        int r = rr[k];
        if ((__ldg(&g_flags[r >> 5]) >> (r & 31)) & 1u) {
            int owner = g_rowmap[r] - 1;
            int idx = atomicAdd(&g_cnt[owner], 1);
            if (idx < MAXDEG)
                g_edges[(size_t)owner * MAXDEG + idx] =
                    make_int2(cc[k], __float_as_int(vv[k]));
        }
    }
}

// ---------------------------------------------------------------------------
// K3 (PDL): one warp per slot. Pre-sync: slot row + e0 row (inputs only).
// Post-sync: lane-parallel bucket load, shfl-broadcast accumulate with 4
// gathers in flight, blend, write out, reset flags. No atomics, no REDG.
// ---------------------------------------------------------------------------
__global__ void __launch_bounds__(256)
k_accum(const int* __restrict__ users,
        const int* __restrict__ pos,
        const int* __restrict__ neg,
        const float* __restrict__ user_emb,
        const float* __restrict__ item_emb,
        float* __restrict__ out) {
    int gtid = blockIdx.x * blockDim.x + threadIdx.x;
    int warp = gtid >> 5;
    int lane = gtid & 31;
    bool valid = (warp < NSLOTS);

    int r = 0;
    float2 e = make_float2(0.f, 0.f);
    if (valid) {
        r = slot_row(warp, users, pos, neg);   // input-only: safe pre-sync
        const float* e0 = (r < N_USER) ? (user_emb + (size_t)r * D)
                                       : (item_emb + (size_t)(r - N_USER) * D);
        e = __ldg(reinterpret_cast<const float2*>(e0) + lane);
    }

    cudaGridDependencySynchronize();           // wait for K2's buckets
    if (!valid) return;

    if (lane == 0) g_flags[r >> 5] = 0u;       // racing zeros — benign
    int owner = g_rowmap[r] - 1;               // broadcast load
    int cnt = g_cnt[owner];                    // broadcast load
    cnt = cnt < MAXDEG ? cnt : MAXDEG;
    const int2* bucket = g_edges + (size_t)owner * MAXDEG;

    float ax = 0.0f, ay = 0.0f;

#define PROC(J)                                                              \
    {                                                                        \
        int   cc = __shfl_sync(0xffffffffu, be.x, (J));                      \
        float vv = __int_as_float(__shfl_sync(0xffffffffu, be.y, (J)));      \
        const float* src = (cc < N_USER)                                     \
                               ? (user_emb + (size_t)cc * D)                 \
                               : (item_emb + (size_t)(cc - N_USER) * D);     \
        float2 ev = __ldg(reinterpret_cast<const float2*>(src) + lane);      \
        ax = fmaf(vv, ev.x, ax);                                             \
        ay = fmaf(vv, ev.y, ay);                                             \
    }

    for (int bse = 0; bse < cnt; bse += 32) {
        int rem = cnt - bse;
        int m = rem < 32 ? rem : 32;
        int2 be = (lane < m) ? __ldg(bucket + bse + lane) : make_int2(0, 0);
        int j = 0;
        for (; j + 4 <= m; j += 4) {
            PROC(j) PROC(j + 1) PROC(j + 2) PROC(j + 3)
        }
        for (; j < m; j++) PROC(j)
    }
#undef PROC

    float2 o;
    o.x = (e.x + 3.0f * ax) * 0.25f;
    o.y = (e.y + 3.0f * ay) * 0.25f;
    reinterpret_cast<float2*>(out)[(size_t)warp * (D / 2) + lane] = o;
}

// ---------------------------------------------------------------------------
// launch: K1 normal; K2, K3 PDL-chained.
// ---------------------------------------------------------------------------
extern "C" void kernel_launch(void* const* d_in, const int* in_sizes, int n_in,
                              void* d_out, int out_size) {
    const int*   users    = (const int*)d_in[0];
    const int*   pos      = (const int*)d_in[1];
    const int*   neg      = (const int*)d_in[2];
    // d_in[3] mask, d_in[4] norm_adj: unused placeholders
    const float* user_emb = (const float*)d_in[5];
    const float* item_emb = (const float*)d_in[6];
    const int*   adj_row  = (const int*)d_in[7];
    const int*   adj_col  = (const int*)d_in[8];
    const float* adj_val  = (const float*)d_in[9];
    float* out = (float*)d_out;

    (void)in_sizes; (void)n_in; (void)out_size;

    // K1: claim (tiny)
    k_claim<<<(NSLOTS + 255) / 256, 256>>>(users, pos, neg);

    cudaLaunchAttribute attrs[1];
    attrs[0].id = cudaLaunchAttributeProgrammaticStreamSerialization;
    attrs[0].val.programmaticStreamSerializationAllowed = 1;

    // K2: build buckets (PDL; edge stream prefetched pre-sync)
    {
        cudaLaunchConfig_t cfg = {};
        cfg.gridDim  = dim3((NNZ + EPB - 1) / EPB);     // 3907
        cfg.blockDim = dim3(SCAN_THREADS);
        cfg.attrs = attrs;
        cfg.numAttrs = 1;
        cudaLaunchKernelEx(&cfg, k_build, adj_row, adj_col, adj_val);
    }
    // K3: accumulate + blend + write (PDL; e0 rows prefetched pre-sync)
    {
        cudaLaunchConfig_t cfg = {};
        cfg.gridDim  = dim3((NSLOTS * 32 + 255) / 256); // 1536
        cfg.blockDim = dim3(256);
        cfg.attrs = attrs;
        cfg.numAttrs = 1;
        cudaLaunchKernelEx(&cfg, k_accum, users, pos, neg,
                           user_emb, item_emb, out);
    }
}

// round 12
// speedup vs baseline: 1.0049x; 1.0049x over previous
#include <cuda_runtime.h>
#include <cuda_bf16.h>
#include <cstdint>

#define N_USER 100000
#define N_ITEM 50000
#define N_TOTAL (N_USER + N_ITEM)   // 150000
#define D 64
#define NNZ 4000000
#define B 2048
#define NEG (4 * B)                  // 8192
#define NSLOTS (B + B + NEG)         // 12288
#define NWORDS ((N_TOTAL + 31) / 32) // 4688 words = 18.75 KB bitset
#define MAXDEG 128                   // mean deg ~26.7; P(>127) ~ 1e-42

#define EPT 4
#define SCAN_THREADS 256
#define EPB (SCAN_THREADS * EPT)     // 1024 edges per block

// Device scratch (zero-init at load).
// g_rowmap: row -> owner slot + 1. Never reset (only freshly flagged rows probed).
// g_cnt: per-slot bucket fill; zeroed in K1 each call.
// g_flags: needed-row bitset; K3 restores all-zero each call.
__device__ int      g_rowmap[N_TOTAL];                 // 600 KB
__device__ int      g_cnt[NSLOTS];
__device__ int2     g_edges[(size_t)NSLOTS * MAXDEG];  // (col, val bits), 12.6 MB
__device__ unsigned g_flags[NWORDS];

// slot -> global row id in [0, N_TOTAL)
__device__ __forceinline__ int slot_row(int s, const int* __restrict__ users,
                                        const int* __restrict__ pos,
                                        const int* __restrict__ neg) {
    if (s < B) return users[s];
    if (s < 2 * B) return N_USER + pos[s - B];
    return N_USER + neg[s - 2 * B];
}

// ---------------------------------------------------------------------------
// K1: claim rows + set flags + zero bucket counters. Tiny.
// ---------------------------------------------------------------------------
__global__ void k_claim(const int* __restrict__ users,
                        const int* __restrict__ pos,
                        const int* __restrict__ neg) {
    int s = blockIdx.x * blockDim.x + threadIdx.x;
    if (s >= NSLOTS) return;
    int r = slot_row(s, users, pos, neg);
    g_rowmap[r] = s + 1;                       // racing stores: any winner OK
    g_cnt[s] = 0;
    atomicOr(&g_flags[r >> 5], 1u << (r & 31));
}

// ---------------------------------------------------------------------------
// K2 (PDL): stream all edge records pre-sync, then probe flags and append
// hits (col, val) to the final owner's bucket. No REDG anywhere.
// ---------------------------------------------------------------------------
__global__ void __launch_bounds__(SCAN_THREADS)
k_build(const int* __restrict__ adj_row,
        const int* __restrict__ adj_col,
        const float* __restrict__ adj_val) {
    int base = (blockIdx.x * SCAN_THREADS + threadIdx.x) * EPT;
    int4 r4 = make_int4(0, 0, 0, 0);
    int4 c4 = make_int4(0, 0, 0, 0);
    float4 v4 = make_float4(0.f, 0.f, 0.f, 0.f);
    bool valid = (base < NNZ);                 // NNZ % 4 == 0 -> full int4
    if (valid) {                               // dependency-free prefetch
        r4 = __ldcs(reinterpret_cast<const int4*>(adj_row) + (base >> 2));
        c4 = __ldcs(reinterpret_cast<const int4*>(adj_col) + (base >> 2));
        v4 = __ldcs(reinterpret_cast<const float4*>(adj_val) + (base >> 2));
    }

    cudaGridDependencySynchronize();           // wait for K1 (flags/rowmap/cnt)

    if (!valid) return;
    int   rr[EPT] = {r4.x, r4.y, r4.z, r4.w};
    int   cc[EPT] = {c4.x, c4.y, c4.z, c4.w};
    float vv[EPT] = {v4.x, v4.y, v4.z, v4.w};
#pragma unroll
    for (int k = 0; k < EPT; k++) {
        int r = rr[k];
        if ((__ldg(&g_flags[r >> 5]) >> (r & 31)) & 1u) {
            int owner = g_rowmap[r] - 1;
            int idx = atomicAdd(&g_cnt[owner], 1);
            if (idx < MAXDEG)
                g_edges[(size_t)owner * MAXDEG + idx] =
                    make_int2(cc[k], __float_as_int(vv[k]));
        }
    }
}

// ---------------------------------------------------------------------------
// K3 (PDL): TWO warps per slot. Each warp accumulates half the bucket
// (full 256B row per gather, 4 gathers in flight); partials combined via
// smem; even warp blends with e0 and writes out. Zero pre-sync footprint.
// Grid is exact: blocks * 8 warps == NSLOTS * 2.
// ---------------------------------------------------------------------------
__global__ void __launch_bounds__(256)
k_accum(const int* __restrict__ users,
        const int* __restrict__ pos,
        const int* __restrict__ neg,
        const float* __restrict__ user_emb,
        const float* __restrict__ item_emb,
        float* __restrict__ out) {
    __shared__ float2 s_part[4][32];           // one entry per slot-pair in block

    int tid   = threadIdx.x;
    int lane  = tid & 31;
    int wid   = tid >> 5;                      // 0..7
    int pair  = wid >> 1;                      // 0..3 (slot within block)
    int part  = wid & 1;                       // 0 = leader, 1 = helper
    int slot  = (blockIdx.x * 4) + pair;       // global slot (exact fit)

    cudaGridDependencySynchronize();           // minimal pre-sync footprint

    int r = slot_row(slot, users, pos, neg);   // broadcast load
    if (part == 0 && lane == 0) g_flags[r >> 5] = 0u;   // racing zeros — benign
    int owner = g_rowmap[r] - 1;               // broadcast load
    int cnt = g_cnt[owner];                    // broadcast load
    cnt = cnt < MAXDEG ? cnt : MAXDEG;
    int hlf = (cnt + 1) >> 1;
    int beg = part ? hlf : 0;
    int end = part ? cnt : hlf;
    const int2* bucket = g_edges + (size_t)owner * MAXDEG;

    float ax = 0.0f, ay = 0.0f;

#define PROC(J)                                                              \
    {                                                                        \
        int   cc = __shfl_sync(0xffffffffu, be.x, (J));                      \
        float vv = __int_as_float(__shfl_sync(0xffffffffu, be.y, (J)));      \
        const float* src = (cc < N_USER)                                     \
                               ? (user_emb + (size_t)cc * D)                 \
                               : (item_emb + (size_t)(cc - N_USER) * D);     \
        float2 ev = __ldg(reinterpret_cast<const float2*>(src) + lane);      \
        ax = fmaf(vv, ev.x, ax);                                             \
        ay = fmaf(vv, ev.y, ay);                                             \
    }

    for (int bse = beg; bse < end; bse += 32) {
        int m = end - bse; m = m < 32 ? m : 32;
        int2 be = (lane < m) ? __ldg(bucket + bse + lane) : make_int2(0, 0);
        int j = 0;
        for (; j + 4 <= m; j += 4) {
            PROC(j) PROC(j + 1) PROC(j + 2) PROC(j + 3)
        }
        for (; j < m; j++) PROC(j)
    }
#undef PROC

    if (part == 1) {
        s_part[pair][lane] = make_float2(ax, ay);
    }
    __syncthreads();
    if (part == 0) {
        float2 p = s_part[pair][lane];
        ax += p.x; ay += p.y;

        const float* e0 = (r < N_USER) ? (user_emb + (size_t)r * D)
                                       : (item_emb + (size_t)(r - N_USER) * D);
        float2 e = __ldg(reinterpret_cast<const float2*>(e0) + lane);
        float2 o;
        o.x = (e.x + 3.0f * ax) * 0.25f;
        o.y = (e.y + 3.0f * ay) * 0.25f;
        reinterpret_cast<float2*>(out)[(size_t)slot * (D / 2) + lane] = o;
    }
}

// ---------------------------------------------------------------------------
// launch: K1 normal; K2, K3 PDL-chained.
// ---------------------------------------------------------------------------
extern "C" void kernel_launch(void* const* d_in, const int* in_sizes, int n_in,
                              void* d_out, int out_size) {
    const int*   users    = (const int*)d_in[0];
    const int*   pos      = (const int*)d_in[1];
    const int*   neg      = (const int*)d_in[2];
    // d_in[3] mask, d_in[4] norm_adj: unused placeholders
    const float* user_emb = (const float*)d_in[5];
    const float* item_emb = (const float*)d_in[6];
    const int*   adj_row  = (const int*)d_in[7];
    const int*   adj_col  = (const int*)d_in[8];
    const float* adj_val  = (const float*)d_in[9];
    float* out = (float*)d_out;

    (void)in_sizes; (void)n_in; (void)out_size;

    // K1: claim (tiny)
    k_claim<<<(NSLOTS + 255) / 256, 256>>>(users, pos, neg);

    cudaLaunchAttribute attrs[1];
    attrs[0].id = cudaLaunchAttributeProgrammaticStreamSerialization;
    attrs[0].val.programmaticStreamSerializationAllowed = 1;

    // K2: build buckets (PDL; edge stream prefetched pre-sync)
    {
        cudaLaunchConfig_t cfg = {};
        cfg.gridDim  = dim3((NNZ + EPB - 1) / EPB);     // 3907
        cfg.blockDim = dim3(SCAN_THREADS);
        cfg.attrs = attrs;
        cfg.numAttrs = 1;
        cudaLaunchKernelEx(&cfg, k_build, adj_row, adj_col, adj_val);
    }
    // K3: accumulate (2 warps/slot) + blend + write (PDL; no pre-sync work)
    {
        cudaLaunchConfig_t cfg = {};
        cfg.gridDim  = dim3(NSLOTS / 4);                // 3072 (exact)
        cfg.blockDim = dim3(256);
        cfg.attrs = attrs;
        cfg.numAttrs = 1;
        cudaLaunchKernelEx(&cfg, k_accum, users, pos, neg,
                           user_emb, item_emb, out);
    }
}

// round 13
// speedup vs baseline: 1.1803x; 1.1745x over previous
#include <cuda_runtime.h>
#include <cuda_bf16.h>
#include <cstdint>

#define N_USER 100000
#define N_ITEM 50000
#define N_TOTAL (N_USER + N_ITEM)   // 150000
#define D 64
#define NNZ 4000000
#define B 2048
#define NEG (4 * B)                  // 8192
#define NSLOTS (B + B + NEG)         // 12288
#define NWORDS ((N_TOTAL + 31) / 32) // 4688 words = 18.75 KB bitset

#define EPT 4
#define SCAN_THREADS 256
#define EPB (SCAN_THREADS * EPT)     // 1024 edges per block
#define MAX_HITS 192                 // mean ~80/chunk, sd ~8.6 -> 13 sigma margin

// Device scratch (zero-init at load).
// g_acc2: dense per-owner-slot accumulator (3 MB, L2-hot), zeroed in K2.
// g_rowmap: row -> owner slot + 1. Never reset (only freshly flagged rows probed).
// g_flags: needed-row bitset; K4 restores all-zero each call.
__device__ float    g_acc2[(size_t)NSLOTS * D];   // 3 MB
__device__ int      g_rowmap[N_TOTAL];            // 600 KB
__device__ unsigned g_flags[NWORDS];              // 18.75 KB

// slot -> global row id in [0, N_TOTAL)
__device__ __forceinline__ int slot_row(int s, const int* __restrict__ users,
                                        const int* __restrict__ pos,
                                        const int* __restrict__ neg) {
    if (s < B) return users[s];
    if (s < 2 * B) return N_USER + pos[s - B];
    return N_USER + neg[s - 2 * B];
}

// ---------------------------------------------------------------------------
// K2: coalesced-zero dense accumulator + claim rows + set flags.
// Triggers programmatic launch completion IMMEDIATELY so K3's blocks launch
// and stream the 48 MB edge arrays concurrently with this kernel.
// ---------------------------------------------------------------------------
__global__ void k_prep(const int* __restrict__ users,
                       const int* __restrict__ pos,
                       const int* __restrict__ neg) {
    cudaTriggerProgrammaticLaunchCompletion();      // release K3's launch NOW
    int gtid = blockIdx.x * blockDim.x + threadIdx.x;
    int nthr = gridDim.x * blockDim.x;
    float4 z = make_float4(0.f, 0.f, 0.f, 0.f);
    for (int i = gtid; i < NSLOTS * D / 4; i += nthr)
        reinterpret_cast<float4*>(g_acc2)[i] = z;
    if (gtid < NSLOTS) {
        int r = slot_row(gtid, users, pos, neg);
        g_rowmap[r] = gtid + 1;                     // racing stores: any winner OK
        atomicOr(&g_flags[r >> 5], 1u << (r & 31));
    }
}

// ---------------------------------------------------------------------------
// K3 (PDL): prefetch edge data BEFORE the grid dependency sync, then probe
// flags, stage hits (col, val, owner) in smem, drain with float4 gather +
// red.v4 into the hot dense accumulator.
// ---------------------------------------------------------------------------
__global__ void __launch_bounds__(SCAN_THREADS)
k_spmm(const int* __restrict__ adj_row,
       const int* __restrict__ adj_col,
       const float* __restrict__ adj_val,
       const float* __restrict__ user_emb,
       const float* __restrict__ item_emb) {
    __shared__ int  s_cnt;
    __shared__ int4 s_hits[MAX_HITS];               // (col, val bits, owner, -)

    int tid = threadIdx.x;
    if (tid == 0) s_cnt = 0;

    // ---- dependency-free prefetch: full edge records, streaming ----
    int base = (blockIdx.x * SCAN_THREADS + tid) * EPT;
    int4 r4 = make_int4(0, 0, 0, 0);
    int4 c4 = make_int4(0, 0, 0, 0);
    float4 v4 = make_float4(0.f, 0.f, 0.f, 0.f);
    bool valid = (base < NNZ);                      // NNZ % 4 == 0 -> full int4
    if (valid) {
        r4 = __ldcs(reinterpret_cast<const int4*>(adj_row) + (base >> 2));
        c4 = __ldcs(reinterpret_cast<const int4*>(adj_col) + (base >> 2));
        v4 = __ldcs(reinterpret_cast<const float4*>(adj_val) + (base >> 2));
    }

    // Wait for K2 (flags / rowmap / zeroed acc) to be complete.
    cudaGridDependencySynchronize();
    __syncthreads();                                // s_cnt visible

    if (valid) {
        int   rr[EPT] = {r4.x, r4.y, r4.z, r4.w};
        int   cc[EPT] = {c4.x, c4.y, c4.z, c4.w};
        float vv[EPT] = {v4.x, v4.y, v4.z, v4.w};
#pragma unroll
        for (int k = 0; k < EPT; k++) {
            int r = rr[k];
            if ((__ldg(&g_flags[r >> 5]) >> (r & 31)) & 1u) {
                int owner = g_rowmap[r] - 1;
                int idx = atomicAdd(&s_cnt, 1);
                if (idx < MAX_HITS)
                    s_hits[idx] = make_int4(cc[k], __float_as_int(vv[k]), owner, 0);
            }
        }
    }
    __syncthreads();

    // ---- drain: half-warp per hit, two hits in flight ----
    int n = s_cnt < MAX_HITS ? s_cnt : MAX_HITS;
    int lane = tid & 31;
    int wid  = tid >> 5;
    int half = lane >> 4;
    int l4   = lane & 15;

    for (int h = wid * 2 + half; h < n; h += 32) {
        int4 ha = s_hits[h];
        const float* srcA = (ha.x < N_USER)
                                ? (user_emb + (size_t)ha.x * D)
                                : (item_emb + (size_t)(ha.x - N_USER) * D);
        float4 eA = __ldg(reinterpret_cast<const float4*>(srcA) + l4);

        int h2 = h + 16;
        bool hasB = (h2 < n);
        int4 hb = hasB ? s_hits[h2] : make_int4(0, 0, 0, 0);
        float4 eB = make_float4(0.f, 0.f, 0.f, 0.f);
        const float* srcB = (hb.x < N_USER)
                                ? (user_emb + (size_t)hb.x * D)
                                : (item_emb + (size_t)(hb.x - N_USER) * D);
        if (hasB) eB = __ldg(reinterpret_cast<const float4*>(srcB) + l4);

        float vA = __int_as_float(ha.y);
        float* dstA = g_acc2 + (size_t)ha.z * D + l4 * 4;
        asm volatile("red.global.add.v4.f32 [%0], {%1, %2, %3, %4};"
                     :: "l"(dstA),
                        "f"(vA * eA.x), "f"(vA * eA.y),
                        "f"(vA * eA.z), "f"(vA * eA.w)
                     : "memory");
        if (hasB) {
            float vB = __int_as_float(hb.y);
            float* dstB = g_acc2 + (size_t)hb.z * D + l4 * 4;
            asm volatile("red.global.add.v4.f32 [%0], {%1, %2, %3, %4};"
                         :: "l"(dstB),
                            "f"(vB * eB.x), "f"(vB * eB.y),
                            "f"(vB * eB.z), "f"(vB * eB.w)
                         : "memory");
        }
    }
}

// ---------------------------------------------------------------------------
// K4 (PDL): pre-sync loads of slot ids + e0 rows (inputs only), then sync,
// then acc2 read + blend + store + flag reset.
// ---------------------------------------------------------------------------
__global__ void k_gather(const int* __restrict__ users,
                         const int* __restrict__ pos,
                         const int* __restrict__ neg,
                         const float* __restrict__ user_emb,
                         const float* __restrict__ item_emb,
                         float* __restrict__ out) {
    int gtid = blockIdx.x * blockDim.x + threadIdx.x;
    int warp = gtid >> 5;
    int lane = gtid & 31;
    int half = lane >> 4;
    int l4   = lane & 15;
    int s = warp * 2 + half;

    int r = 0;
    float4 e = make_float4(0.f, 0.f, 0.f, 0.f);
    bool valid = (s < NSLOTS);
    if (valid) {
        r = slot_row(s, users, pos, neg);           // input-only: safe pre-sync
        const float* e0 = (r < N_USER) ? (user_emb + (size_t)r * D)
                                       : (item_emb + (size_t)(r - N_USER) * D);
        e = __ldg(reinterpret_cast<const float4*>(e0) + l4);
    }

    cudaGridDependencySynchronize();                // wait for K3's REDGs
    if (!valid) return;

    if (l4 == 0) g_flags[r >> 5] = 0u;              // racing zeros — benign
    int owner = g_rowmap[r] - 1;

    float4 a = *(reinterpret_cast<const float4*>(g_acc2 + (size_t)owner * D) + l4);
    float4 o;
    o.x = (e.x + 3.0f * a.x) * 0.25f;
    o.y = (e.y + 3.0f * a.y) * 0.25f;
    o.z = (e.z + 3.0f * a.z) * 0.25f;
    o.w = (e.w + 3.0f * a.w) * 0.25f;
    reinterpret_cast<float4*>(out)[(size_t)s * (D / 4) + l4] = o;
}

// ---------------------------------------------------------------------------
// launch: K2 normal (with early trigger); K3, K4 PDL.
// ---------------------------------------------------------------------------
extern "C" void kernel_launch(void* const* d_in, const int* in_sizes, int n_in,
                              void* d_out, int out_size) {
    const int*   users    = (const int*)d_in[0];
    const int*   pos      = (const int*)d_in[1];
    const int*   neg      = (const int*)d_in[2];
    // d_in[3] mask, d_in[4] norm_adj: unused placeholders
    const float* user_emb = (const float*)d_in[5];
    const float* item_emb = (const float*)d_in[6];
    const int*   adj_row  = (const int*)d_in[7];
    const int*   adj_col  = (const int*)d_in[8];
    const float* adj_val  = (const float*)d_in[9];
    float* out = (float*)d_out;

    (void)in_sizes; (void)n_in; (void)out_size;

    // K2: normal launch (triggers PDL release at its start)
    k_prep<<<512, 256>>>(users, pos, neg);

    cudaLaunchAttribute attrs[1];
    attrs[0].id = cudaLaunchAttributeProgrammaticStreamSerialization;
    attrs[0].val.programmaticStreamSerializationAllowed = 1;

    // K3: PDL launch (edge stream prefetched pre-sync, overlaps k_prep)
    {
        cudaLaunchConfig_t cfg = {};
        cfg.gridDim  = dim3((NNZ + EPB - 1) / EPB);   // 3907
        cfg.blockDim = dim3(SCAN_THREADS);
        cfg.attrs = attrs;
        cfg.numAttrs = 1;
        cudaLaunchKernelEx(&cfg, k_spmm, adj_row, adj_col, adj_val,
                           user_emb, item_emb);
    }
    // K4: PDL launch (e0 rows prefetched pre-sync, overlaps k_spmm teardown)
    {
        int warps = (NSLOTS + 1) / 2;                 // 6144
        cudaLaunchConfig_t cfg = {};
        cfg.gridDim  = dim3((warps * 32 + 255) / 256);  // 768
        cfg.blockDim = dim3(256);
        cfg.attrs = attrs;
        cfg.numAttrs = 1;
        cudaLaunchKernelEx(&cfg, k_gather, users, pos, neg,
                           user_emb, item_emb, out);
    }
}